// round 13
// baseline (speedup 1.0000x reference)
#include <cuda_runtime.h>
#include <cstdint>

// CRF loss: mean_b( logZ_b - gold_b );  B=256, T=1024, C=64
// Scaled-domain forward: p_{t+1} = (E^T p_t) ∘ W_t / c_t,  logZ += log2 c_t.
// FOUR warps per chain, HALF a dot product per thread (32 MACs = 16 FFMA2):
// per-warp issue/step drops ~3x vs 1-warp design; halves combined by
// intra-pair shfl_xor(1). One 128-thread named barrier per step.
// Block = 256 thr = 2 chains; grid 128. p halves padded 16B apart in smem so
// even/odd-lane broadcast loads hit disjoint banks. Reduction fused.

#define BD 256
#define TD 1024
#define CD 64
#define LOG2E 1.4426950408889634f
#define LN2   0.6931471805599453f

typedef unsigned long long ull;

__device__ float        g_partial[BD];
__device__ unsigned int g_done = 0;

__device__ __forceinline__ float fast_exp2(float x) {
    float y; asm("ex2.approx.ftz.f32 %0, %1;" : "=f"(y) : "f"(x)); return y;
}
__device__ __forceinline__ float fast_log2(float x) {
    float y; asm("lg2.approx.ftz.f32 %0, %1;" : "=f"(y) : "f"(x)); return y;
}
__device__ __forceinline__ float fast_rcp(float x) {
    float y; asm("rcp.approx.ftz.f32 %0, %1;" : "=f"(y) : "f"(x)); return y;
}
__device__ __forceinline__ ull pack2(float lo, float hi) {
    ull r; asm("mov.b64 %0, {%1, %2};" : "=l"(r) : "f"(lo), "f"(hi)); return r;
}
__device__ __forceinline__ ull ffma2(ull a, ull b, ull c) {
    ull d; asm("fma.rn.f32x2 %0, %1, %2, %3;" : "=l"(d) : "l"(a), "l"(b), "l"(c));
    return d;
}
__device__ __forceinline__ ull fadd2(ull a, ull b) {
    ull d; asm("add.rn.f32x2 %0, %1, %2;" : "=l"(d) : "l"(a), "l"(b));
    return d;
}
__device__ __forceinline__ float2 unpack2(ull v) {
    float2 f; asm("mov.b64 {%0, %1}, %2;" : "=f"(f.x), "=f"(f.y) : "l"(v));
    return f;
}

// per-chain barrier: 128 threads (4 warps), ids 1 and 2
#define CHBAR(c) asm volatile("bar.sync %0, 128;" :: "r"((c) + 1) : "memory")

// One forward step. T_/SLOT_ compile-time. PF_: refill ring slot with t+4.
#define STEP_BODY(PF_, T_, SLOT_)                                              \
    {                                                                          \
        const float W  = Wring[(SLOT_)];                                       \
        const float mt = mring[(SLOT_)];                                       \
        if (PF_) {                                                             \
            const int tpf = (T_) + 4;                                          \
            Wring[(SLOT_)] = fast_exp2(em[tpf * CD + tag] * LOG2E);            \
            mring[(SLOT_)] = mk[tpf];                                          \
        }                                                                      \
        const float* pc = &psh[ch][cur][0];                                    \
        const float  c  = pc[0];         /* normalizer: tag 0 at index 0 */    \
        const float  r  = fast_rcp(c);                                         \
        logAcc += fast_log2(c);                                                \
        const float Wr = W * r;                                                \
        const float* ph = pc + pbase;    /* this thread's 32-input half */     \
        ull a0 = 0ull, a1 = 0ull, a2 = 0ull, a3 = 0ull;                        \
        _Pragma("unroll")                                                      \
        for (int i = 0; i < 32; i += 8) {                                      \
            ulonglong2 qa = *(const ulonglong2*)&ph[i];                        \
            ulonglong2 qb = *(const ulonglong2*)&ph[i + 4];                    \
            a0 = ffma2(qa.x, Ep[i / 2 + 0], a0);                               \
            a1 = ffma2(qa.y, Ep[i / 2 + 1], a1);                               \
            a2 = ffma2(qb.x, Ep[i / 2 + 2], a2);                               \
            a3 = ffma2(qb.y, Ep[i / 2 + 3], a3);                               \
        }                                                                      \
        const ull    ta = fadd2(fadd2(a0, a1), fadd2(a2, a3));                 \
        const float2 u  = unpack2(ta);                                         \
        const float  sh = u.x + u.y;                                           \
        const float  s  = sh + __shfl_xor_sync(0xffffffffu, sh, 1);            \
        myp = (mt > 0.f) ? s * Wr : myp * r;                                   \
        if (half == 0) psh[ch][cur ^ 1][ix_tag] = myp;                         \
        CHBAR(ch);                                                             \
        cur ^= 1;                                                              \
    }

__global__ __launch_bounds__(256)
void crf_fused_kernel(const float* __restrict__ emissions,
                      const float* __restrict__ transitions,
                      const float* __restrict__ start_t,
                      const float* __restrict__ end_t,
                      const int*   __restrict__ tags,
                      const float* __restrict__ mask,
                      float*       __restrict__ out)
{
    // p layout per chain/buffer: floats [0..31] = tags 0..31, 16B pad,
    // floats [36..67] = tags 32..63  -> even/odd lane loads bank-disjoint.
    __shared__ __align__(16) float psh[2][2][72];
    __shared__ float        gsm[2][4];
    __shared__ int          csm[2][4];
    __shared__ float        vsm[2][4];
    __shared__ float        rsm[8];
    __shared__ unsigned int last_flag;

    const int ch   = threadIdx.x >> 7;        // chain 0/1
    const int ct   = threadIdx.x & 127;       // thread within chain
    const int wc   = ct >> 5;                 // warp within chain
    const int lane = threadIdx.x & 31;
    const int tag  = ct >> 1;                 // tag owned by this pair
    const int half = ct & 1;                  // which 32-input half
    const int b    = blockIdx.x * 2 + ch;

    const int ix_tag = tag + ((tag >> 5) << 2);   // padded store index
    const int pbase  = half * 36;                 // padded half base (floats)

    const float* em = emissions + (size_t)b * TD * CD;
    const int*   tg = tags      + (size_t)b * TD;
    const float* mk = mask      + (size_t)b * TD;

    // ---- E block: rows [half*32, half*32+32) of column `tag`, packed ----
    ull Ep[16];
    #pragma unroll
    for (int k = 0; k < 16; k++) {
        const int i0 = half * 32 + 2 * k;
        Ep[k] = pack2(fast_exp2(transitions[i0 * CD + tag] * LOG2E),
                      fast_exp2(transitions[(i0 + 1) * CD + tag] * LOG2E));
    }

    // ---- gold score (128 threads stride T) ----
    float gp  = 0.f;
    int   cnt = 0;
    for (int t = ct; t < TD; t += 128) {
        float m = mk[t];
        cnt += (int)m;
        if (t >= 1) {
            int tc = tg[t], tp = tg[t - 1];
            gp += m * (em[t * CD + tc] + transitions[tp * CD + tc]);
        }
    }
    #pragma unroll
    for (int off = 16; off; off >>= 1) {
        gp  += __shfl_xor_sync(0xffffffffu, gp,  off);
        cnt += __shfl_xor_sync(0xffffffffu, cnt, off);
    }
    if (lane == 0) { gsm[ch][wc] = gp; csm[ch][wc] = cnt; }

    // ---- init (t = 0), linear domain ----
    float myp = fast_exp2((start_t[tag] + em[tag]) * LOG2E);
    if (half == 0) psh[ch][0][ix_tag] = myp;

    // ---- prefetch ring (4 deep): W = exp(emit[tag]), mask ----
    float Wring[4], mring[4];
    #pragma unroll
    for (int t0 = 1; t0 <= 4; t0++) {
        Wring[t0 & 3] = fast_exp2(em[t0 * CD + tag] * LOG2E);
        mring[t0 & 3] = mk[t0];
    }

    CHBAR(ch);   // psh[ch][0], gsm/csm visible within chain

    float gold = 0.f;
    if (ct == 0) {
        int seqlen = csm[ch][0] + csm[ch][1] + csm[ch][2] + csm[ch][3];
        int li = seqlen - 1; if (li < 0) li = 0;
        const int tfirst = tg[0], tlast = tg[li];
        gold = gsm[ch][0] + gsm[ch][1] + gsm[ch][2] + gsm[ch][3]
             + start_t[tfirst] + em[tfirst] + end_t[tlast];
    }

    // ---- recursion ----
    float logAcc = 0.f;
    int   cur    = 0;

    // main: t = 1..1016 (254 chunks of 4), unconditional prefetch (max 1020)
    for (int tb = 1; tb <= 1013; tb += 4) {
        STEP_BODY(1, tb + 0, 1) STEP_BODY(1, tb + 1, 2)
        STEP_BODY(1, tb + 2, 3) STEP_BODY(1, tb + 3, 0)
    }
    // t = 1017..1019: prefetch 1021..1023
    STEP_BODY(1, 1017, 1) STEP_BODY(1, 1018, 2) STEP_BODY(1, 1019, 3)
    // t = 1020..1023: no prefetch
    STEP_BODY(0, 1020, 0) STEP_BODY(0, 1021, 1)
    STEP_BODY(0, 1022, 2) STEP_BODY(0, 1023, 3)

    // ---- final: logZ = LN2 * (logAcc + log2(sum_j p_j * exp(end_j))) ----
    float v = (half == 0) ? myp * fast_exp2(end_t[tag] * LOG2E) : 0.f;
    #pragma unroll
    for (int off = 16; off; off >>= 1)
        v += __shfl_xor_sync(0xffffffffu, v, off);
    if (lane == 0) vsm[ch][wc] = v;
    CHBAR(ch);

    if (ct == 0) {
        const float vv = (vsm[ch][0] + vsm[ch][1]) + (vsm[ch][2] + vsm[ch][3]);
        g_partial[b] = (logAcc + fast_log2(vv)) * LN2 - gold;
    }

    // ---- fused deterministic mean reduction (last block) ----
    __syncthreads();                       // both chains' g_partial writes done
    if (threadIdx.x == 0) {
        __threadfence();                   // publish this block's writes
        unsigned int tk = atomicAdd(&g_done, 1u);
        last_flag = (tk == gridDim.x - 1) ? 1u : 0u;
    }
    __syncthreads();

    if (last_flag) {
        __threadfence();                   // acquire all blocks' writes
        float s = g_partial[threadIdx.x];
        #pragma unroll
        for (int off = 16; off; off >>= 1)
            s += __shfl_xor_sync(0xffffffffu, s, off);
        if (lane == 0) rsm[threadIdx.x >> 5] = s;
        __syncthreads();
        if (threadIdx.x < 8) {
            float sv = rsm[threadIdx.x];
            #pragma unroll
            for (int off = 4; off; off >>= 1)
                sv += __shfl_xor_sync(0x000000ffu, sv, off);
            if (threadIdx.x == 0) {
                out[0] = sv * (1.0f / BD);
                g_done = 0;                // reset for next graph replay
            }
        }
    }
}

extern "C" void kernel_launch(void* const* d_in, const int* in_sizes, int n_in,
                              void* d_out, int out_size)
{
    const float* emissions   = (const float*)d_in[0];
    const float* transitions = (const float*)d_in[1];
    const float* start_t     = (const float*)d_in[2];
    const float* end_t       = (const float*)d_in[3];
    const int*   tags        = (const int*)  d_in[4];
    const float* mask        = (const float*)d_in[5];
    float* out = (float*)d_out;

    crf_fused_kernel<<<BD / 2, 256>>>(emissions, transitions, start_t, end_t,
                                      tags, mask, out);
}

// round 14
// speedup vs baseline: 1.0166x; 1.0166x over previous
#include <cuda_runtime.h>
#include <cuda_fp16.h>
#include <cstdint>

// CRF loss: mean_b( logZ_b - gold_b );  B=256, T=1024, C=64
// Scaled-domain forward with FP16 matvec on the HFMA2 pipe (32 MAC/cyc/warp,
// 2x the fp32 FMA rate that capped every previous config at ~330 cyc/step).
// p stored in smem as DUPLICATED half2 (v_i,v_i); E columns as half2
// (E[i][j0],E[i][j1]) in regs -> 64 HFMA2 computes both tags' dots at once.
// Per masked step p carries an extra 2^-6 scale (overflow headroom),
// compensated exactly by +6*n_masked in log2 space. logAcc/gold/exp/log/rcp
// remain fp32. One warp per chain; __syncwarp only. Reduction fused.

#define BD 256
#define TD 1024
#define CD 64
#define LOG2E 1.4426950408889634f
#define LN2   0.6931471805599453f
#define LAM   0.015625f            /* 2^-6 */
#define LAMW  6.0f                 /* -log2(LAM) */

__device__ float        g_partial[BD];
__device__ unsigned int g_done = 0;

__device__ __forceinline__ float fast_exp2(float x) {
    float y; asm("ex2.approx.ftz.f32 %0, %1;" : "=f"(y) : "f"(x)); return y;
}
__device__ __forceinline__ float fast_log2(float x) {
    float y; asm("lg2.approx.ftz.f32 %0, %1;" : "=f"(y) : "f"(x)); return y;
}
__device__ __forceinline__ float fast_rcp(float x) {
    float y; asm("rcp.approx.ftz.f32 %0, %1;" : "=f"(y) : "f"(x)); return y;
}
__device__ __forceinline__ __half2 u2h(unsigned int u) {
    __half2 h; *reinterpret_cast<unsigned int*>(&h) = u; return h;
}
__device__ __forceinline__ unsigned int h2u(__half2 h) {
    return *reinterpret_cast<unsigned int*>(&h);
}

// One forward step. T_/SLOT_ compile-time. PF_: refill ring slot with t+4.
#define STEP_BODY(PF_, T_, SLOT_)                                              \
    {                                                                          \
        const float W0 = Wring0[(SLOT_)];                                      \
        const float W1 = Wring1[(SLOT_)];                                      \
        const float mt = mring[(SLOT_)];                                       \
        if (PF_) {                                                             \
            const int tpf = (T_) + 4;                                          \
            Wring0[(SLOT_)] = fast_exp2(em[tpf * CD + j0] * LOG2E);            \
            Wring1[(SLOT_)] = fast_exp2(em[tpf * CD + j1] * LOG2E);            \
            mring[(SLOT_)]  = mk[tpf];                                         \
        }                                                                      \
        const unsigned int* pd = psh[w][cur];                                  \
        const float c = __low2float(u2h(pd[0]));    /* normalizer = v[0] */    \
        const float r = fast_rcp(c);                                           \
        logAcc += fast_log2(c);                                                \
        const float rl = r * LAM;                                              \
        const __half2 wr2 = __floats2half2_rn(W0 * rl, W1 * rl);               \
        const __half2 rr2 = __float2half2_rn(r);                               \
        __half2 a0 = __float2half2_rn(0.f), a1 = a0, a2 = a0, a3 = a0;         \
        __half2 a4 = a0, a5 = a0, a6 = a0, a7 = a0;                            \
        _Pragma("unroll")                                                      \
        for (int i = 0; i < CD; i += 8) {                                      \
            const uint4 qa = *(const uint4*)&pd[i];                            \
            const uint4 qb = *(const uint4*)&pd[i + 4];                        \
            a0 = __hfma2(u2h(qa.x), Eh[i + 0], a0);                            \
            a1 = __hfma2(u2h(qa.y), Eh[i + 1], a1);                            \
            a2 = __hfma2(u2h(qa.z), Eh[i + 2], a2);                            \
            a3 = __hfma2(u2h(qa.w), Eh[i + 3], a3);                            \
            a4 = __hfma2(u2h(qb.x), Eh[i + 4], a4);                            \
            a5 = __hfma2(u2h(qb.y), Eh[i + 5], a5);                            \
            a6 = __hfma2(u2h(qb.z), Eh[i + 6], a6);                            \
            a7 = __hfma2(u2h(qb.w), Eh[i + 7], a7);                            \
        }                                                                      \
        const __half2 ssum = __hadd2(__hadd2(__hadd2(a0, a1), __hadd2(a2, a3)),\
                                     __hadd2(__hadd2(a4, a5), __hadd2(a6, a7)));\
        const __half2 qn = __hmul2(ssum, wr2);                                 \
        myq = (mt > 0.f) ? qn : __hmul2(myq, rr2);                             \
        const unsigned int mq = h2u(myq);                                      \
        unsigned int* pn = psh[w][cur ^ 1];                                    \
        pn[j0] = __byte_perm(mq, mq, 0x1010);   /* (v_j0, v_j0) */             \
        pn[j1] = __byte_perm(mq, mq, 0x3232);   /* (v_j1, v_j1) */             \
        __syncwarp();                                                          \
        cur ^= 1;                                                              \
    }

__global__ __launch_bounds__(128)
void crf_fused_kernel(const float* __restrict__ emissions,
                      const float* __restrict__ transitions,
                      const float* __restrict__ start_t,
                      const float* __restrict__ end_t,
                      const int*   __restrict__ tags,
                      const float* __restrict__ mask,
                      float*       __restrict__ out)
{
    // dup-p buffers: word i = half2(v_i, v_i); double-buffered per chain
    __shared__ __align__(16) unsigned int psh[4][2][CD];
    __shared__ float        rsm[4];
    __shared__ unsigned int last_flag;

    const int w    = threadIdx.x >> 5;    // chain within block (0..3)
    const int lane = threadIdx.x & 31;
    const int b    = blockIdx.x * 4 + w;  // batch index
    const int j0   = lane;
    const int j1   = lane + 32;

    const float* em = emissions + (size_t)b * TD * CD;
    const int*   tg = tags      + (size_t)b * TD;
    const float* mk = mask      + (size_t)b * TD;

    // ---- E columns in fp16: Eh[i] = half2(exp(T[i][j0]), exp(T[i][j1])) ----
    __half2 Eh[CD];
    #pragma unroll
    for (int i = 0; i < CD; i++) {
        const float* ri = transitions + i * CD;
        Eh[i] = __floats2half2_rn(fast_exp2(ri[j0] * LOG2E),
                                  fast_exp2(ri[j1] * LOG2E));
    }

    // ---- gold score (32 threads stride T), fp32 exact ----
    float gp  = 0.f;
    int   cnt = 0;
    for (int t = lane; t < TD; t += 32) {
        float m = mk[t];
        cnt += (int)m;
        if (t >= 1) {
            int tc = tg[t], tp = tg[t - 1];
            gp += m * (em[t * CD + tc] + transitions[tp * CD + tc]);
        }
    }
    #pragma unroll
    for (int off = 16; off; off >>= 1) {
        gp  += __shfl_xor_sync(0xffffffffu, gp,  off);
        cnt += __shfl_xor_sync(0xffffffffu, cnt, off);
    }
    int lastidx = cnt - 1; if (lastidx < 0) lastidx = 0;
    const int   nmask  = cnt - (int)mk[0];          // # masked-in steps t>=1
    const int   tfirst = tg[0], tlast = tg[lastidx];
    const float gold   = gp + start_t[tfirst] + em[tfirst] + end_t[tlast];

    // ---- init (t = 0): v = exp(start + emit0), fp16 pair ----
    float v0f = fast_exp2((start_t[j0] + em[j0]) * LOG2E);
    float v1f = fast_exp2((start_t[j1] + em[j1]) * LOG2E);
    __half2 myq = __floats2half2_rn(v0f, v1f);
    {
        const unsigned int mq = h2u(myq);
        psh[w][0][j0] = __byte_perm(mq, mq, 0x1010);
        psh[w][0][j1] = __byte_perm(mq, mq, 0x3232);
    }

    // ---- prefetch ring (4 deep): W = exp(emit), mask, fp32 ----
    float Wring0[4], Wring1[4], mring[4];
    #pragma unroll
    for (int t0 = 1; t0 <= 4; t0++) {
        Wring0[t0 & 3] = fast_exp2(em[t0 * CD + j0] * LOG2E);
        Wring1[t0 & 3] = fast_exp2(em[t0 * CD + j1] * LOG2E);
        mring[t0 & 3]  = mk[t0];
    }
    __syncwarp();   // psh[w][0] visible

    // ---- recursion ----
    float logAcc = 0.f;
    int   cur    = 0;

    // main: t = 1..1016 (254 chunks of 4), unconditional prefetch (max 1020)
    for (int tb = 1; tb <= 1013; tb += 4) {
        STEP_BODY(1, tb + 0, 1) STEP_BODY(1, tb + 1, 2)
        STEP_BODY(1, tb + 2, 3) STEP_BODY(1, tb + 3, 0)
    }
    // t = 1017..1019: prefetch 1021..1023
    STEP_BODY(1, 1017, 1) STEP_BODY(1, 1018, 2) STEP_BODY(1, 1019, 3)
    // t = 1020..1023: no prefetch
    STEP_BODY(0, 1020, 0) STEP_BODY(0, 1021, 1)
    STEP_BODY(0, 1022, 2) STEP_BODY(0, 1023, 3)

    // ---- final: logZ = LN2*(logAcc + log2(sum_j v_j e^end_j) + 6*nmask) ----
    float v = __low2float(myq)  * fast_exp2(end_t[j0] * LOG2E)
            + __high2float(myq) * fast_exp2(end_t[j1] * LOG2E);
    #pragma unroll
    for (int off = 16; off; off >>= 1)
        v += __shfl_xor_sync(0xffffffffu, v, off);

    if (lane == 0)
        g_partial[b] = (logAcc + fast_log2(v) + LAMW * (float)nmask) * LN2
                     - gold;

    // ---- fused deterministic mean reduction (last block) ----
    __syncthreads();                       // all 4 chains' g_partial writes done
    if (threadIdx.x == 0) {
        __threadfence();                   // publish this block's writes
        unsigned int tk = atomicAdd(&g_done, 1u);
        last_flag = (tk == gridDim.x - 1) ? 1u : 0u;
    }
    __syncthreads();

    if (last_flag) {
        __threadfence();                   // acquire all blocks' writes
        float s = g_partial[threadIdx.x] + g_partial[threadIdx.x + 128];
        #pragma unroll
        for (int off = 16; off; off >>= 1)
            s += __shfl_xor_sync(0xffffffffu, s, off);
        if (lane == 0) rsm[w] = s;
        __syncthreads();
        if (threadIdx.x == 0) {
            out[0] = (rsm[0] + rsm[1] + rsm[2] + rsm[3]) * (1.0f / BD);
            g_done = 0;                    // reset for next graph replay
        }
    }
}

extern "C" void kernel_launch(void* const* d_in, const int* in_sizes, int n_in,
                              void* d_out, int out_size)
{
    const float* emissions   = (const float*)d_in[0];
    const float* transitions = (const float*)d_in[1];
    const float* start_t     = (const float*)d_in[2];
    const float* end_t       = (const float*)d_in[3];
    const int*   tags        = (const int*)  d_in[4];
    const float* mask        = (const float*)d_in[5];
    float* out = (float*)d_out;

    crf_fused_kernel<<<BD / 4, 128>>>(emissions, transitions, start_t, end_t,
                                      tags, mask, out);
}

// round 15
// speedup vs baseline: 1.0217x; 1.0051x over previous
#include <cuda_runtime.h>
#include <cstdint>

// CRF loss: mean_b( logZ_b - gold_b );  B=256, T=1024, C=64
// Scaled-domain forward: p_{t+1} = (E^T p_t) ∘ W_t / c_t,  logZ += log2 c_t.
// One warp per chain (2 tags/thread). KEY FIX vs R12: the emission ring now
// stores RAW loads; ex2 cooking happens 7 steps after the LDG (≈1600 cyc >
// DRAM latency), so the warp never stalls on memory inside a step. The old
// ring converted in the same breath as the load -> ~300-cycle stall per step.
// Normalizer (r, log2 c, W*r, mask) still staged one step ahead via shfl.
// Grid 64 x 128thr: 4 chains/block, 1 warp/SMSP. Reduction fused.

#define BD 256
#define TD 1024
#define CD 64
#define LOG2E 1.4426950408889634f
#define LN2   0.6931471805599453f

typedef unsigned long long ull;

__device__ float        g_partial[BD];
__device__ unsigned int g_done = 0;

__device__ __forceinline__ float fast_exp2(float x) {
    float y; asm("ex2.approx.ftz.f32 %0, %1;" : "=f"(y) : "f"(x)); return y;
}
__device__ __forceinline__ float fast_log2(float x) {
    float y; asm("lg2.approx.ftz.f32 %0, %1;" : "=f"(y) : "f"(x)); return y;
}
__device__ __forceinline__ float fast_rcp(float x) {
    float y; asm("rcp.approx.ftz.f32 %0, %1;" : "=f"(y) : "f"(x)); return y;
}
__device__ __forceinline__ ull pack2(float lo, float hi) {
    ull r; asm("mov.b64 %0, {%1, %2};" : "=l"(r) : "f"(lo), "f"(hi)); return r;
}
__device__ __forceinline__ ull ffma2(ull a, ull b, ull c) {
    ull d; asm("fma.rn.f32x2 %0, %1, %2, %3;" : "=l"(d) : "l"(a), "l"(b), "l"(c));
    return d;
}
__device__ __forceinline__ ull fadd2(ull a, ull b) {
    ull d; asm("add.rn.f32x2 %0, %1, %2;" : "=l"(d) : "l"(a), "l"(b));
    return d;
}
__device__ __forceinline__ float2 unpack2(ull v) {
    float2 f; asm("mov.b64 {%0, %1}, %2;" : "=f"(f.x), "=f"(f.y) : "l"(v));
    return f;
}

// One forward step. T_/SLOT_/NSLOT_ compile-time; SLOT_ = T_&7, NSLOT_=(T_+1)&7.
// PF_: refill raw ring slot with t+8 (LDG only; cooked 7 steps later).
#define STEP_BODY(PF_, T_, SLOT_, NSLOT_)                                      \
    {                                                                          \
        logAcc += lgcS;                                                        \
        /* cook W for step T_+1 from raw loaded 7 steps ago: no LDG stall */   \
        const float W0n = fast_exp2(rawW0[(NSLOT_)] * LOG2E);                  \
        const float W1n = fast_exp2(rawW1[(NSLOT_)] * LOG2E);                  \
        const float mtn = rawm[(NSLOT_)];                                      \
        if (PF_) {   /* pure LDG refill; consumer is 7 steps downstream */     \
            const int tpf = (T_) + 8;                                          \
            rawW0[(SLOT_)] = em[tpf * CD + j0];                                \
            rawW1[(SLOT_)] = em[tpf * CD + j1];                                \
            rawm[(SLOT_)]  = mk[tpf];                                          \
        }                                                                      \
        const float* pc = psh[w][cur];                                         \
        ull a0 = 0ull, a1 = 0ull, a2 = 0ull, a3 = 0ull;                        \
        ull b0 = 0ull, b1 = 0ull, b2 = 0ull, b3 = 0ull;                        \
        _Pragma("unroll")                                                      \
        for (int i = 0; i < CD; i += 8) {                                      \
            ulonglong2 qa = *(const ulonglong2*)&pc[i];                        \
            ulonglong2 qb = *(const ulonglong2*)&pc[i + 4];                    \
            a0 = ffma2(qa.x, E0p[i / 2 + 0], a0);                              \
            b0 = ffma2(qa.x, E1p[i / 2 + 0], b0);                              \
            a1 = ffma2(qa.y, E0p[i / 2 + 1], a1);                              \
            b1 = ffma2(qa.y, E1p[i / 2 + 1], b1);                              \
            a2 = ffma2(qb.x, E0p[i / 2 + 2], a2);                              \
            b2 = ffma2(qb.x, E1p[i / 2 + 2], b2);                              \
            a3 = ffma2(qb.y, E0p[i / 2 + 3], a3);                              \
            b3 = ffma2(qb.y, E1p[i / 2 + 3], b3);                              \
        }                                                                      \
        const ull ta = fadd2(fadd2(a0, a1), fadd2(a2, a3));                    \
        const ull tb2 = fadd2(fadd2(b0, b1), fadd2(b2, b3));                   \
        const float2 ua = unpack2(ta);                                         \
        const float2 ub = unpack2(tb2);                                        \
        const float s0 = ua.x + ua.y;                                          \
        const float s1 = ub.x + ub.y;                                          \
        myp0 = (mtS > 0.f) ? s0 * Wr0S : myp0 * rS;                            \
        myp1 = (mtS > 0.f) ? s1 * Wr1S : myp1 * rS;                            \
        float* pn = psh[w][cur ^ 1];                                           \
        pn[j0] = myp0;                                                         \
        pn[j1] = myp1;                                                         \
        const float cNx = __shfl_sync(0xffffffffu, myp0, 0);                   \
        rS   = fast_rcp(cNx);                                                  \
        lgcS = fast_log2(cNx);                                                 \
        mtS  = mtn;                                                            \
        Wr0S = W0n * rS;                                                       \
        Wr1S = W1n * rS;                                                       \
        __syncwarp();                                                          \
        cur ^= 1;                                                              \
    }

__global__ __launch_bounds__(128)
void crf_fused_kernel(const float* __restrict__ emissions,
                      const float* __restrict__ transitions,
                      const float* __restrict__ start_t,
                      const float* __restrict__ end_t,
                      const int*   __restrict__ tags,
                      const float* __restrict__ mask,
                      float*       __restrict__ out)
{
    __shared__ __align__(16) float psh[4][2][CD];  // [chain][buf][tag]
    __shared__ float        rsm[4];
    __shared__ unsigned int last_flag;

    const int w    = threadIdx.x >> 5;    // chain within block (0..3)
    const int lane = threadIdx.x & 31;
    const int b    = blockIdx.x * 4 + w;  // batch index
    const int j0   = lane;
    const int j1   = lane + 32;

    const float* em = emissions + (size_t)b * TD * CD;
    const int*   tg = tags      + (size_t)b * TD;
    const float* mk = mask      + (size_t)b * TD;

    // ---- packed E columns: E?p[k] = {exp(T[2k][j?]), exp(T[2k+1][j?])} ----
    ull E0p[CD / 2], E1p[CD / 2];
    #pragma unroll
    for (int k = 0; k < CD / 2; k++) {
        const float* r0 = transitions + (2 * k)     * CD;
        const float* r1 = transitions + (2 * k + 1) * CD;
        E0p[k] = pack2(fast_exp2(r0[j0] * LOG2E), fast_exp2(r1[j0] * LOG2E));
        E1p[k] = pack2(fast_exp2(r0[j1] * LOG2E), fast_exp2(r1[j1] * LOG2E));
    }

    // ---- gold score (32 threads stride T) ----
    float gp  = 0.f;
    int   cnt = 0;
    for (int t = lane; t < TD; t += 32) {
        float m = mk[t];
        cnt += (int)m;
        if (t >= 1) {
            int tc = tg[t], tp = tg[t - 1];
            gp += m * (em[t * CD + tc] + transitions[tp * CD + tc]);
        }
    }
    #pragma unroll
    for (int off = 16; off; off >>= 1) {
        gp  += __shfl_xor_sync(0xffffffffu, gp,  off);
        cnt += __shfl_xor_sync(0xffffffffu, cnt, off);
    }
    int lastidx = cnt - 1; if (lastidx < 0) lastidx = 0;
    const int tfirst = tg[0], tlast = tg[lastidx];              // broadcast LDG
    const float gold = gp + start_t[tfirst] + em[tfirst] + end_t[tlast];

    // ---- init (t = 0), linear domain ----
    float myp0 = fast_exp2((start_t[j0] + em[j0]) * LOG2E);
    float myp1 = fast_exp2((start_t[j1] + em[j1]) * LOG2E);
    psh[w][0][j0] = myp0;
    psh[w][0][j1] = myp1;

    // ---- RAW ring (8 deep): unconverted emissions + mask ----
    float rawW0[8], rawW1[8], rawm[8];
    #pragma unroll
    for (int t0 = 1; t0 <= 8; t0++) {
        rawW0[t0 & 7] = em[t0 * CD + j0];
        rawW1[t0 & 7] = em[t0 * CD + j1];
        rawm[t0 & 7]  = mk[t0];
    }

    // ---- stage for step t=1 ----
    float cN   = __shfl_sync(0xffffffffu, myp0, 0);   // c_0 = p_0[0]
    float rS   = fast_rcp(cN);
    float lgcS = fast_log2(cN);
    float mtS  = rawm[1];
    float Wr0S = fast_exp2(rawW0[1] * LOG2E) * rS;
    float Wr1S = fast_exp2(rawW1[1] * LOG2E) * rS;

    __syncwarp();   // psh[w][0] visible

    // ---- recursion ----
    float logAcc = 0.f;
    int   cur    = 0;

    // main loop: t = 1..1008 (126 chunks of 8), unconditional refill
    for (int tb = 1; tb <= 1001; tb += 8) {
        STEP_BODY(1, tb + 0, 1, 2) STEP_BODY(1, tb + 1, 2, 3)
        STEP_BODY(1, tb + 2, 3, 4) STEP_BODY(1, tb + 3, 4, 5)
        STEP_BODY(1, tb + 4, 5, 6) STEP_BODY(1, tb + 5, 6, 7)
        STEP_BODY(1, tb + 6, 7, 0) STEP_BODY(1, tb + 7, 0, 1)
    }
    // t = 1009..1015: refill t+8 = 1017..1023 (still in range)
    STEP_BODY(1, 1009, 1, 2) STEP_BODY(1, 1010, 2, 3) STEP_BODY(1, 1011, 3, 4)
    STEP_BODY(1, 1012, 4, 5) STEP_BODY(1, 1013, 5, 6) STEP_BODY(1, 1014, 6, 7)
    STEP_BODY(1, 1015, 7, 0)
    // t = 1016..1023: no refill (cook of step 1024 reads stale slot; unused)
    STEP_BODY(0, 1016, 0, 1) STEP_BODY(0, 1017, 1, 2) STEP_BODY(0, 1018, 2, 3)
    STEP_BODY(0, 1019, 3, 4) STEP_BODY(0, 1020, 4, 5) STEP_BODY(0, 1021, 5, 6)
    STEP_BODY(0, 1022, 6, 7) STEP_BODY(0, 1023, 7, 0)

    // ---- final: logZ = LN2 * (logAcc + log2(sum_j p_j * exp(end_j))) ----
    float v = myp0 * fast_exp2(end_t[j0] * LOG2E)
            + myp1 * fast_exp2(end_t[j1] * LOG2E);
    #pragma unroll
    for (int off = 16; off; off >>= 1)
        v += __shfl_xor_sync(0xffffffffu, v, off);

    if (lane == 0)
        g_partial[b] = (logAcc + fast_log2(v)) * LN2 - gold;

    // ---- fused deterministic mean reduction (last block) ----
    __syncthreads();                       // all 4 chains' g_partial writes done
    if (threadIdx.x == 0) {
        __threadfence();                   // publish this block's writes
        unsigned int tk = atomicAdd(&g_done, 1u);
        last_flag = (tk == gridDim.x - 1) ? 1u : 0u;
    }
    __syncthreads();

    if (last_flag) {
        __threadfence();                   // acquire all blocks' writes
        float s = g_partial[threadIdx.x] + g_partial[threadIdx.x + 128];
        #pragma unroll
        for (int off = 16; off; off >>= 1)
            s += __shfl_xor_sync(0xffffffffu, s, off);
        if (lane == 0) rsm[w] = s;
        __syncthreads();
        if (threadIdx.x == 0) {
            out[0] = (rsm[0] + rsm[1] + rsm[2] + rsm[3]) * (1.0f / BD);
            g_done = 0;                    // reset for next graph replay
        }
    }
}

extern "C" void kernel_launch(void* const* d_in, const int* in_sizes, int n_in,
                              void* d_out, int out_size)
{
    const float* emissions   = (const float*)d_in[0];
    const float* transitions = (const float*)d_in[1];
    const float* start_t     = (const float*)d_in[2];
    const float* end_t       = (const float*)d_in[3];
    const int*   tags        = (const int*)  d_in[4];
    const float* mask        = (const float*)d_in[5];
    float* out = (float*)d_out;

    crf_fused_kernel<<<BD / 4, 128>>>(emissions, transitions, start_t, end_t,
                                      tags, mask, out);
}

// round 16
// speedup vs baseline: 1.2049x; 1.1793x over previous
#include <cuda_runtime.h>
#include <cstdint>

// CRF loss: mean_b( logZ_b - gold_b );  B=256, T=1024, C=64
// Scaled-domain forward with LAZY renormalization: divide by c=p[0] only every
// 4th step (fp32 headroom: worst-case 4-step growth ~1e18 on <=1.6e5 spread,
// far below 3.4e38). Deletes per-step rcp+lg2 (2 MUFU) + shfl staging.
// Intra-warp step sync via named bar.sync id=(w+1), count=32 (3-cyc floor)
// instead of WARPSYNC (~23). One warp per chain (2 tags/thread), raw emission
// ring (LDG decoupled from ex2 by 8 steps). Grid 64 x 128thr. Reduction fused.

#define BD 256
#define TD 1024
#define CD 64
#define LOG2E 1.4426950408889634f
#define LN2   0.6931471805599453f

typedef unsigned long long ull;

__device__ float        g_partial[BD];
__device__ unsigned int g_done = 0;

__device__ __forceinline__ float fast_exp2(float x) {
    float y; asm("ex2.approx.ftz.f32 %0, %1;" : "=f"(y) : "f"(x)); return y;
}
__device__ __forceinline__ float fast_log2(float x) {
    float y; asm("lg2.approx.ftz.f32 %0, %1;" : "=f"(y) : "f"(x)); return y;
}
__device__ __forceinline__ float fast_rcp(float x) {
    float y; asm("rcp.approx.ftz.f32 %0, %1;" : "=f"(y) : "f"(x)); return y;
}
__device__ __forceinline__ ull pack2(float lo, float hi) {
    ull r; asm("mov.b64 %0, {%1, %2};" : "=l"(r) : "f"(lo), "f"(hi)); return r;
}
__device__ __forceinline__ ull ffma2(ull a, ull b, ull c) {
    ull d; asm("fma.rn.f32x2 %0, %1, %2, %3;" : "=l"(d) : "l"(a), "l"(b), "l"(c));
    return d;
}
__device__ __forceinline__ ull fadd2(ull a, ull b) {
    ull d; asm("add.rn.f32x2 %0, %1, %2;" : "=l"(d) : "l"(a), "l"(b));
    return d;
}
__device__ __forceinline__ float2 unpack2(ull v) {
    float2 f; asm("mov.b64 {%0, %1}, %2;" : "=f"(f.x), "=f"(f.y) : "l"(v));
    return f;
}

// single-warp named barrier (drains STS; floor ~3 cyc)
#define WBAR() asm volatile("bar.sync %0, 32;" :: "r"(w + 1) : "memory")

// One forward step. T_/SLOT_ compile-time (SLOT_ = T_&7).
// RN_: renormalize this step (T_ % 4 == 1). PF_: refill raw ring with t+8.
#define STEP_BODY(RN_, PF_, T_, SLOT_)                                         \
    {                                                                          \
        float W0 = fast_exp2(rawW0[(SLOT_)] * LOG2E);                          \
        float W1 = fast_exp2(rawW1[(SLOT_)] * LOG2E);                          \
        const float mt = rawm[(SLOT_)];                                        \
        if (PF_) {   /* pure LDG; consumer (ex2) is 8 steps downstream */      \
            const int tpf = (T_) + 8;                                          \
            rawW0[(SLOT_)] = em[tpf * CD + j0];                                \
            rawW1[(SLOT_)] = em[tpf * CD + j1];                                \
            rawm[(SLOT_)]  = mk[tpf];                                          \
        }                                                                      \
        const float* pc = psh[w][cur];                                         \
        float r = 1.f;                                                         \
        if (RN_) {                                                             \
            const float c = pc[0];        /* broadcast LDS, off-chain */       \
            r = fast_rcp(c);                                                   \
            logAcc += fast_log2(c);                                            \
            W0 *= r;                                                           \
            W1 *= r;                                                           \
        }                                                                      \
        ull a0 = 0ull, a1 = 0ull, a2 = 0ull, a3 = 0ull;                        \
        ull b0 = 0ull, b1 = 0ull, b2 = 0ull, b3 = 0ull;                        \
        _Pragma("unroll")                                                      \
        for (int i = 0; i < CD; i += 8) {                                      \
            ulonglong2 qa = *(const ulonglong2*)&pc[i];                        \
            ulonglong2 qb = *(const ulonglong2*)&pc[i + 4];                    \
            a0 = ffma2(qa.x, E0p[i / 2 + 0], a0);                              \
            b0 = ffma2(qa.x, E1p[i / 2 + 0], b0);                              \
            a1 = ffma2(qa.y, E0p[i / 2 + 1], a1);                              \
            b1 = ffma2(qa.y, E1p[i / 2 + 1], b1);                              \
            a2 = ffma2(qb.x, E0p[i / 2 + 2], a2);                              \
            b2 = ffma2(qb.x, E1p[i / 2 + 2], b2);                              \
            a3 = ffma2(qb.y, E0p[i / 2 + 3], a3);                              \
            b3 = ffma2(qb.y, E1p[i / 2 + 3], b3);                              \
        }                                                                      \
        const ull ta = fadd2(fadd2(a0, a1), fadd2(a2, a3));                    \
        const ull tb2 = fadd2(fadd2(b0, b1), fadd2(b2, b3));                   \
        const float2 ua = unpack2(ta);                                         \
        const float2 ub = unpack2(tb2);                                        \
        const float s0 = ua.x + ua.y;                                          \
        const float s1 = ub.x + ub.y;                                          \
        if (RN_) {   /* divide whole carried vector by c (mask-consistent) */  \
            myp0 = (mt > 0.f) ? s0 * W0 : myp0 * r;                            \
            myp1 = (mt > 0.f) ? s1 * W1 : myp1 * r;                            \
        } else {                                                               \
            myp0 = (mt > 0.f) ? s0 * W0 : myp0;                                \
            myp1 = (mt > 0.f) ? s1 * W1 : myp1;                                \
        }                                                                      \
        float* pn = psh[w][cur ^ 1];                                           \
        pn[j0] = myp0;                                                         \
        pn[j1] = myp1;                                                         \
        WBAR();                                                                \
        cur ^= 1;                                                              \
    }

__global__ __launch_bounds__(128)
void crf_fused_kernel(const float* __restrict__ emissions,
                      const float* __restrict__ transitions,
                      const float* __restrict__ start_t,
                      const float* __restrict__ end_t,
                      const int*   __restrict__ tags,
                      const float* __restrict__ mask,
                      float*       __restrict__ out)
{
    __shared__ __align__(16) float psh[4][2][CD];  // [chain][buf][tag]
    __shared__ float        rsm[4];
    __shared__ unsigned int last_flag;

    const int w    = threadIdx.x >> 5;    // chain within block (0..3)
    const int lane = threadIdx.x & 31;
    const int b    = blockIdx.x * 4 + w;  // batch index
    const int j0   = lane;
    const int j1   = lane + 32;

    const float* em = emissions + (size_t)b * TD * CD;
    const int*   tg = tags      + (size_t)b * TD;
    const float* mk = mask      + (size_t)b * TD;

    // ---- packed E columns: E?p[k] = {exp(T[2k][j?]), exp(T[2k+1][j?])} ----
    ull E0p[CD / 2], E1p[CD / 2];
    #pragma unroll
    for (int k = 0; k < CD / 2; k++) {
        const float* r0 = transitions + (2 * k)     * CD;
        const float* r1 = transitions + (2 * k + 1) * CD;
        E0p[k] = pack2(fast_exp2(r0[j0] * LOG2E), fast_exp2(r1[j0] * LOG2E));
        E1p[k] = pack2(fast_exp2(r0[j1] * LOG2E), fast_exp2(r1[j1] * LOG2E));
    }

    // ---- gold score (32 threads stride T) ----
    float gp  = 0.f;
    int   cnt = 0;
    for (int t = lane; t < TD; t += 32) {
        float m = mk[t];
        cnt += (int)m;
        if (t >= 1) {
            int tc = tg[t], tp = tg[t - 1];
            gp += m * (em[t * CD + tc] + transitions[tp * CD + tc]);
        }
    }
    #pragma unroll
    for (int off = 16; off; off >>= 1) {
        gp  += __shfl_xor_sync(0xffffffffu, gp,  off);
        cnt += __shfl_xor_sync(0xffffffffu, cnt, off);
    }
    int lastidx = cnt - 1; if (lastidx < 0) lastidx = 0;
    const int tfirst = tg[0], tlast = tg[lastidx];              // broadcast LDG
    const float gold = gp + start_t[tfirst] + em[tfirst] + end_t[tlast];

    // ---- init (t = 0), linear domain ----
    float myp0 = fast_exp2((start_t[j0] + em[j0]) * LOG2E);
    float myp1 = fast_exp2((start_t[j1] + em[j1]) * LOG2E);
    psh[w][0][j0] = myp0;
    psh[w][0][j1] = myp1;

    // ---- RAW ring (8 deep): unconverted emissions + mask ----
    float rawW0[8], rawW1[8], rawm[8];
    #pragma unroll
    for (int t0 = 1; t0 <= 8; t0++) {
        rawW0[t0 & 7] = em[t0 * CD + j0];
        rawW1[t0 & 7] = em[t0 * CD + j1];
        rawm[t0 & 7]  = mk[t0];
    }

    WBAR();   // psh[w][0] visible

    // ---- recursion: renorm at t % 4 == 1 (t = 1, 5, ..., 1021) ----
    float logAcc = 0.f;
    int   cur    = 0;

    // main: t = 1..1008 (126 chunks of 8, start t%8==1), unconditional refill
    for (int tb = 1; tb <= 1001; tb += 8) {
        STEP_BODY(1, 1, tb + 0, 1) STEP_BODY(0, 1, tb + 1, 2)
        STEP_BODY(0, 1, tb + 2, 3) STEP_BODY(0, 1, tb + 3, 4)
        STEP_BODY(1, 1, tb + 4, 5) STEP_BODY(0, 1, tb + 5, 6)
        STEP_BODY(0, 1, tb + 6, 7) STEP_BODY(0, 1, tb + 7, 0)
    }
    // t = 1009..1015: refill 1017..1023 (in range). RN at 1009, 1013.
    STEP_BODY(1, 1, 1009, 1) STEP_BODY(0, 1, 1010, 2) STEP_BODY(0, 1, 1011, 3)
    STEP_BODY(0, 1, 1012, 4) STEP_BODY(1, 1, 1013, 5) STEP_BODY(0, 1, 1014, 6)
    STEP_BODY(0, 1, 1015, 7)
    // t = 1016..1023: no refill. RN at 1017, 1021.
    STEP_BODY(0, 0, 1016, 0) STEP_BODY(1, 0, 1017, 1) STEP_BODY(0, 0, 1018, 2)
    STEP_BODY(0, 0, 1019, 3) STEP_BODY(0, 0, 1020, 4) STEP_BODY(1, 0, 1021, 5)
    STEP_BODY(0, 0, 1022, 6) STEP_BODY(0, 0, 1023, 7)

    // ---- final: logZ = LN2 * (logAcc + log2(sum_j p_j * exp(end_j))) ----
    float v = myp0 * fast_exp2(end_t[j0] * LOG2E)
            + myp1 * fast_exp2(end_t[j1] * LOG2E);
    #pragma unroll
    for (int off = 16; off; off >>= 1)
        v += __shfl_xor_sync(0xffffffffu, v, off);

    if (lane == 0)
        g_partial[b] = (logAcc + fast_log2(v)) * LN2 - gold;

    // ---- fused deterministic mean reduction (last block) ----
    __syncthreads();                       // all 4 chains' g_partial writes done
    if (threadIdx.x == 0) {
        __threadfence();                   // publish this block's writes
        unsigned int tk = atomicAdd(&g_done, 1u);
        last_flag = (tk == gridDim.x - 1) ? 1u : 0u;
    }
    __syncthreads();

    if (last_flag) {
        __threadfence();                   // acquire all blocks' writes
        float s = g_partial[threadIdx.x] + g_partial[threadIdx.x + 128];
        #pragma unroll
        for (int off = 16; off; off >>= 1)
            s += __shfl_xor_sync(0xffffffffu, s, off);
        if (lane == 0) rsm[w] = s;
        __syncthreads();
        if (threadIdx.x == 0) {
            out[0] = (rsm[0] + rsm[1] + rsm[2] + rsm[3]) * (1.0f / BD);
            g_done = 0;                    // reset for next graph replay
        }
    }
}

extern "C" void kernel_launch(void* const* d_in, const int* in_sizes, int n_in,
                              void* d_out, int out_size)
{
    const float* emissions   = (const float*)d_in[0];
    const float* transitions = (const float*)d_in[1];
    const float* start_t     = (const float*)d_in[2];
    const float* end_t       = (const float*)d_in[3];
    const int*   tags        = (const int*)  d_in[4];
    const float* mask        = (const float*)d_in[5];
    float* out = (float*)d_out;

    crf_fused_kernel<<<BD / 4, 128>>>(emissions, transitions, start_t, end_t,
                                      tags, mask, out);
}

// round 17
// speedup vs baseline: 1.2443x; 1.0327x over previous
#include <cuda_runtime.h>
#include <cuda_bf16.h>
#include <cstdint>

// CRF loss: mean_b( logZ_b - gold_b );  B=256, T=1024, C=64
// Scaled-domain forward with BF16 matvec. The fp32 FMA pipe imposes a
// 256-cyc/step floor (128 MAC-lane-ops x rt2; fma.rn.f32x2 is double-pumped).
// HFMA2.BF16_V2 does 2 real MACs per rt-2 lane-op -> 128-cyc floor, and bf16
// keeps fp32's exponent range so the 4-step lazy renorm survives.
// Thread owns adjacent tags (2*lane, 2*lane+1): p exchange is ONE bf16x2 word
// (1 STS.32, 8 LDS.128 per step). logAcc/gold/W/rcp/lg2 stay fp32.
// One warp per chain; named 1-warp bar. Raw 8-deep emission ring (LDG
// decoupled from ex2). Grid 64 x 128thr. Reduction fused.

#define BD 256
#define TD 1024
#define CD 64
#define LOG2E 1.4426950408889634f
#define LN2   0.6931471805599453f

__device__ float        g_partial[BD];
__device__ unsigned int g_done = 0;

__device__ __forceinline__ float fast_exp2(float x) {
    float y; asm("ex2.approx.ftz.f32 %0, %1;" : "=f"(y) : "f"(x)); return y;
}
__device__ __forceinline__ float fast_log2(float x) {
    float y; asm("lg2.approx.ftz.f32 %0, %1;" : "=f"(y) : "f"(x)); return y;
}
__device__ __forceinline__ float fast_rcp(float x) {
    float y; asm("rcp.approx.ftz.f32 %0, %1;" : "=f"(y) : "f"(x)); return y;
}
__device__ __forceinline__ __nv_bfloat162 u2b(unsigned int u) {
    __nv_bfloat162 h; *reinterpret_cast<unsigned int*>(&h) = u; return h;
}
__device__ __forceinline__ unsigned int b2u(__nv_bfloat162 h) {
    return *reinterpret_cast<unsigned int*>(&h);
}

// single-warp named barrier (drains STS; floor ~3 cyc)
#define WBAR() asm volatile("bar.sync %0, 32;" :: "r"(w + 1) : "memory")

// One forward step. T_/SLOT_ compile-time (SLOT_ = T_&7).
// RN_: renormalize (T_ % 4 == 1). PF_: refill raw ring with t+8 (pure LDG).
#define STEP_BODY(RN_, PF_, T_, SLOT_)                                         \
    {                                                                          \
        float W0 = fast_exp2(rawW0[(SLOT_)] * LOG2E);                          \
        float W1 = fast_exp2(rawW1[(SLOT_)] * LOG2E);                          \
        const float mt = rawm[(SLOT_)];                                        \
        if (PF_) {                                                             \
            const int tpf = (T_) + 8;                                          \
            rawW0[(SLOT_)] = em[tpf * CD + j0];                                \
            rawW1[(SLOT_)] = em[tpf * CD + j1];                                \
            rawm[(SLOT_)]  = mk[tpf];                                          \
        }                                                                      \
        const unsigned int* pc = psh[w][cur];                                  \
        float r = 1.f;                                                         \
        if (RN_) {                                                             \
            const float c = __bfloat162float(__low2bfloat16(u2b(pc[0])));      \
            r = fast_rcp(c);                                                   \
            logAcc += fast_log2(c);                                            \
            W0 *= r;                                                           \
            W1 *= r;                                                           \
        }                                                                      \
        __nv_bfloat162 z = __floats2bfloat162_rn(0.f, 0.f);                    \
        __nv_bfloat162 a0 = z, a1 = z, a2 = z, a3 = z;                         \
        __nv_bfloat162 b0 = z, b1 = z, b2 = z, b3 = z;                         \
        _Pragma("unroll")                                                      \
        for (int it = 0; it < 8; it++) {                                       \
            const uint4 q = *(const uint4*)&pc[it * 4];                        \
            a0 = __hfma2(u2b(q.x), E0h[it * 4 + 0], a0);                       \
            b0 = __hfma2(u2b(q.x), E1h[it * 4 + 0], b0);                       \
            a1 = __hfma2(u2b(q.y), E0h[it * 4 + 1], a1);                       \
            b1 = __hfma2(u2b(q.y), E1h[it * 4 + 1], b1);                       \
            a2 = __hfma2(u2b(q.z), E0h[it * 4 + 2], a2);                       \
            b2 = __hfma2(u2b(q.z), E1h[it * 4 + 2], b2);                       \
            a3 = __hfma2(u2b(q.w), E0h[it * 4 + 3], a3);                       \
            b3 = __hfma2(u2b(q.w), E1h[it * 4 + 3], b3);                       \
        }                                                                      \
        const __nv_bfloat162 sa =                                              \
            __hadd2(__hadd2(a0, a1), __hadd2(a2, a3));                         \
        const __nv_bfloat162 sb =                                              \
            __hadd2(__hadd2(b0, b1), __hadd2(b2, b3));                         \
        const float s0 = __bfloat162float(__low2bfloat16(sa))                  \
                       + __bfloat162float(__high2bfloat16(sa));                \
        const float s1 = __bfloat162float(__low2bfloat16(sb))                  \
                       + __bfloat162float(__high2bfloat16(sb));                \
        if (RN_) {                                                             \
            myp0 = (mt > 0.f) ? s0 * W0 : myp0 * r;                            \
            myp1 = (mt > 0.f) ? s1 * W1 : myp1 * r;                            \
        } else {                                                               \
            myp0 = (mt > 0.f) ? s0 * W0 : myp0;                                \
            myp1 = (mt > 0.f) ? s1 * W1 : myp1;                                \
        }                                                                      \
        psh[w][cur ^ 1][lane] = b2u(__floats2bfloat162_rn(myp0, myp1));        \
        WBAR();                                                                \
        cur ^= 1;                                                              \
    }

__global__ __launch_bounds__(128)
void crf_fused_kernel(const float* __restrict__ emissions,
                      const float* __restrict__ transitions,
                      const float* __restrict__ start_t,
                      const float* __restrict__ end_t,
                      const int*   __restrict__ tags,
                      const float* __restrict__ mask,
                      float*       __restrict__ out)
{
    // p buffers: word k = bf16x2(v_{2k}, v_{2k+1}); double-buffered per chain
    __shared__ __align__(16) unsigned int psh[4][2][CD / 2];
    __shared__ float        rsm[4];
    __shared__ unsigned int last_flag;

    const int w    = threadIdx.x >> 5;    // chain within block (0..3)
    const int lane = threadIdx.x & 31;
    const int b    = blockIdx.x * 4 + w;  // batch index
    const int j0   = 2 * lane;            // adjacent tag pair
    const int j1   = 2 * lane + 1;

    const float* em = emissions + (size_t)b * TD * CD;
    const int*   tg = tags      + (size_t)b * TD;
    const float* mk = mask      + (size_t)b * TD;

    // ---- E columns in bf16 pairs over input index:
    //      E?h[k] = bf16x2(exp(T[2k][j?]), exp(T[2k+1][j?])) ----
    __nv_bfloat162 E0h[CD / 2], E1h[CD / 2];
    #pragma unroll
    for (int k = 0; k < CD / 2; k++) {
        const float* r0 = transitions + (2 * k)     * CD;
        const float* r1 = transitions + (2 * k + 1) * CD;
        E0h[k] = __floats2bfloat162_rn(fast_exp2(r0[j0] * LOG2E),
                                       fast_exp2(r1[j0] * LOG2E));
        E1h[k] = __floats2bfloat162_rn(fast_exp2(r0[j1] * LOG2E),
                                       fast_exp2(r1[j1] * LOG2E));
    }

    // ---- gold score (32 threads stride T), fp32 exact ----
    float gp  = 0.f;
    int   cnt = 0;
    for (int t = lane; t < TD; t += 32) {
        float m = mk[t];
        cnt += (int)m;
        if (t >= 1) {
            int tc = tg[t], tp = tg[t - 1];
            gp += m * (em[t * CD + tc] + transitions[tp * CD + tc]);
        }
    }
    #pragma unroll
    for (int off = 16; off; off >>= 1) {
        gp  += __shfl_xor_sync(0xffffffffu, gp,  off);
        cnt += __shfl_xor_sync(0xffffffffu, cnt, off);
    }
    int lastidx = cnt - 1; if (lastidx < 0) lastidx = 0;
    const int tfirst = tg[0], tlast = tg[lastidx];              // broadcast LDG
    const float gold = gp + start_t[tfirst] + em[tfirst] + end_t[tlast];

    // ---- init (t = 0), linear domain (fp32 carried, bf16 exchanged) ----
    float myp0 = fast_exp2((start_t[j0] + em[j0]) * LOG2E);
    float myp1 = fast_exp2((start_t[j1] + em[j1]) * LOG2E);
    psh[w][0][lane] = b2u(__floats2bfloat162_rn(myp0, myp1));

    // ---- RAW ring (8 deep): unconverted emissions + mask ----
    float rawW0[8], rawW1[8], rawm[8];
    #pragma unroll
    for (int t0 = 1; t0 <= 8; t0++) {
        rawW0[t0 & 7] = em[t0 * CD + j0];
        rawW1[t0 & 7] = em[t0 * CD + j1];
        rawm[t0 & 7]  = mk[t0];
    }

    WBAR();   // psh[w][0] visible

    // ---- recursion: renorm at t % 4 == 1 ----
    float logAcc = 0.f;
    int   cur    = 0;

    // main: t = 1..1008 (126 chunks of 8), unconditional refill
    for (int tb = 1; tb <= 1001; tb += 8) {
        STEP_BODY(1, 1, tb + 0, 1) STEP_BODY(0, 1, tb + 1, 2)
        STEP_BODY(0, 1, tb + 2, 3) STEP_BODY(0, 1, tb + 3, 4)
        STEP_BODY(1, 1, tb + 4, 5) STEP_BODY(0, 1, tb + 5, 6)
        STEP_BODY(0, 1, tb + 6, 7) STEP_BODY(0, 1, tb + 7, 0)
    }
    // t = 1009..1015: refill 1017..1023 (in range). RN at 1009, 1013.
    STEP_BODY(1, 1, 1009, 1) STEP_BODY(0, 1, 1010, 2) STEP_BODY(0, 1, 1011, 3)
    STEP_BODY(0, 1, 1012, 4) STEP_BODY(1, 1, 1013, 5) STEP_BODY(0, 1, 1014, 6)
    STEP_BODY(0, 1, 1015, 7)
    // t = 1016..1023: no refill. RN at 1017, 1021.
    STEP_BODY(0, 0, 1016, 0) STEP_BODY(1, 0, 1017, 1) STEP_BODY(0, 0, 1018, 2)
    STEP_BODY(0, 0, 1019, 3) STEP_BODY(0, 0, 1020, 4) STEP_BODY(1, 0, 1021, 5)
    STEP_BODY(0, 0, 1022, 6) STEP_BODY(0, 0, 1023, 7)

    // ---- final: logZ = LN2 * (logAcc + log2(sum_j p_j * exp(end_j))) ----
    float v = myp0 * fast_exp2(end_t[j0] * LOG2E)
            + myp1 * fast_exp2(end_t[j1] * LOG2E);
    #pragma unroll
    for (int off = 16; off; off >>= 1)
        v += __shfl_xor_sync(0xffffffffu, v, off);

    if (lane == 0)
        g_partial[b] = (logAcc + fast_log2(v)) * LN2 - gold;

    // ---- fused deterministic mean reduction (last block) ----
    __syncthreads();                       // all 4 chains' g_partial writes done
    if (threadIdx.x == 0) {
        __threadfence();                   // publish this block's writes
        unsigned int tk = atomicAdd(&g_done, 1u);
        last_flag = (tk == gridDim.x - 1) ? 1u : 0u;
    }
    __syncthreads();

    if (last_flag) {
        __threadfence();                   // acquire all blocks' writes
        float s = g_partial[threadIdx.x] + g_partial[threadIdx.x + 128];
        #pragma unroll
        for (int off = 16; off; off >>= 1)
            s += __shfl_xor_sync(0xffffffffu, s, off);
        if (lane == 0) rsm[w] = s;
        __syncthreads();
        if (threadIdx.x == 0) {
            out[0] = (rsm[0] + rsm[1] + rsm[2] + rsm[3]) * (1.0f / BD);
            g_done = 0;                    // reset for next graph replay
        }
    }
}

extern "C" void kernel_launch(void* const* d_in, const int* in_sizes, int n_in,
                              void* d_out, int out_size)
{
    const float* emissions   = (const float*)d_in[0];
    const float* transitions = (const float*)d_in[1];
    const float* start_t     = (const float*)d_in[2];
    const float* end_t       = (const float*)d_in[3];
    const int*   tags        = (const int*)  d_in[4];
    const float* mask        = (const float*)d_in[5];
    float* out = (float*)d_out;

    crf_fused_kernel<<<BD / 4, 128>>>(emissions, transitions, start_t, end_t,
                                      tags, mask, out);
}